// round 13
// baseline (speedup 1.0000x reference)
#include <cuda_runtime.h>
#include <math.h>

#define T_ 256
#define B_ 64
#define P_ 1024
#define H_ 512
#define C_ 16
#define NCH_ (T_ / C_)
#define DECAY 0.999f

// Persistent scratch (static __device__ — no runtime allocation)
__device__ float g_pat[(size_t)B_ * P_ * H_];       // 128 MB carried state
__device__ float g_Q[2][(size_t)B_ * P_ * C_];      // Q[b][p][tau]
__device__ float g_W [(size_t)B_ * C_ * P_];        // W[b][tl][p] = pr*alpha_pre
__device__ float g_Bc[(size_t)B_ * C_ * P_];        // Bc[b][s][p] = f_s at chunk end
__device__ float g_A [B_ * P_];                     // alpha at chunk end
__device__ float g_G [B_ * NCH_ * C_ * C_];         // within-chunk Gram (fp64-accumulated)
__device__ float g_Xn[T_ * B_];                     // ||x_t||^2
__device__ float g_Gam[B_ * C_ * C_];               // gamma[b][tl][s]

// ===========================================================================
// Double-float (compensated fp32) helpers — exact R9 versions.
// ===========================================================================
struct DF { float h, l; };

__device__ __forceinline__ DF df_renorm(float h, float l) {
    float s = __fadd_rn(h, l);
    float e = __fsub_rn(l, __fsub_rn(s, h));
    DF r; r.h = s; r.l = e; return r;
}
__device__ __forceinline__ DF df_two_sum(float a, float b) {
    float s = __fadd_rn(a, b);
    float bb = __fsub_rn(s, a);
    float e = __fadd_rn(__fsub_rn(a, __fsub_rn(s, bb)), __fsub_rn(b, bb));
    DF r; r.h = s; r.l = e; return r;
}
__device__ __forceinline__ DF df_mul(DF a, DF b) {
    float p = __fmul_rn(a.h, b.h);
    float e = fmaf(a.h, b.h, -p);
    e = fmaf(a.h, b.l, e);
    e = fmaf(a.l, b.h, e);
    return df_renorm(p, e);
}
__device__ __forceinline__ DF df_mul_f(DF a, float b) {
    float p = __fmul_rn(a.h, b);
    float e = fmaf(a.h, b, -p);
    e = fmaf(a.l, b, e);
    return df_renorm(p, e);
}
__device__ __forceinline__ DF df_add(DF a, DF b) {
    DF s = df_two_sum(a.h, b.h);
    float e = __fadd_rn(s.l, __fadd_rn(a.l, b.l));
    return df_renorm(s.h, e);
}
__device__ __forceinline__ DF df_add_f(DF a, float b) {
    DF s = df_two_sum(a.h, b);
    float e = __fadd_rn(s.l, a.l);
    return df_renorm(s.h, e);
}

#define D_HI   ((float)0.999)
#define D_LO   ((float)(0.999 - (double)((float)0.999)))
#define D2_HI  ((float)0.998001)
#define D2_LO  ((float)(0.998001 - (double)((float)0.998001)))
#define TD_HI  ((float)1.998)
#define TD_LO  ((float)(1.998 - (double)((float)1.998)))

// ===========================================================================
// Packed f32x2 helpers (sm_103a FFMA2 — per-lane IEEE, bitwise == 2x fmaf)
// ===========================================================================
__device__ __forceinline__ unsigned long long f2_mul(unsigned long long a,
                                                     unsigned long long b) {
    unsigned long long d;
    asm("mul.rn.f32x2 %0, %1, %2;" : "=l"(d) : "l"(a), "l"(b));
    return d;
}
__device__ __forceinline__ unsigned long long f2_fma(unsigned long long a,
                                                     unsigned long long b,
                                                     unsigned long long c) {
    unsigned long long d;
    asm("fma.rn.f32x2 %0, %1, %2, %3;" : "=l"(d) : "l"(a), "l"(b), "l"(c));
    return d;
}
__device__ __forceinline__ float2 f2_unpack(unsigned long long v) {
    float2 r;
    asm("mov.b64 {%0, %1}, %2;" : "=f"(r.x), "=f"(r.y) : "l"(v));
    return r;
}

// ---------------------------------------------------------------------------
// Gram + norms per (b, chunk): fp64 accumulation (tiny volume).
// ---------------------------------------------------------------------------
__global__ __launch_bounds__(256) void xstats_kernel(const float* __restrict__ x) {
    __shared__ float sx[C_ * H_];
    int b = blockIdx.x >> 4;
    int c = blockIdx.x & 15;
    int t0 = c * C_;
    {
        int tau = threadIdx.x >> 4, l16 = threadIdx.x & 15;
        const float4* xs = (const float4*)(x + ((size_t)(t0 + tau) * B_ + b) * H_);
        float4* d = (float4*)(sx + tau * H_);
#pragma unroll
        for (int k = 0; k < 8; k++) d[l16 + 16 * k] = xs[l16 + 16 * k];
    }
    __syncthreads();
    int w = threadIdx.x >> 5, lane = threadIdx.x & 31;
    for (int id = w; id < C_ * C_; id += 8) {
        int s = id >> 4, t = id & 15;
        if (s > t) continue;
        double acc = 0.0;
#pragma unroll
        for (int k = 0; k < 16; k++) {
            int h = lane + 32 * k;
            acc += (double)sx[s * H_ + h] * (double)sx[t * H_ + h];
        }
#pragma unroll
        for (int o = 16; o; o >>= 1) acc += __shfl_xor_sync(~0u, acc, o);
        if (lane == 0) {
            g_G[(((size_t)b * NCH_ + c) * C_ + s) * C_ + t] = (float)acc;
            if (s == t) g_Xn[(t0 + t) * B_ + b] = (float)acc;
        }
    }
}

// ---------------------------------------------------------------------------
// Q[buf][b][p][tau] = src_row(b,p) . x[t0+tau]
// 512 threads, ONE row per warp (16 rows/block, grid B_*64). Per-row math and
// shfl-reduction order identical to R9 -> bitwise-identical Q.
// ---------------------------------------------------------------------------
__global__ __launch_bounds__(512) void qk_kernel(const float* __restrict__ x,
                                                 const float* __restrict__ pat_in,
                                                 int t0, int buf, int useInit) {
    __shared__ float sx[C_ * H_];
    const float* src = useInit ? pat_in : (const float*)g_pat;
    int b = blockIdx.x >> 6;
    int p0 = (blockIdx.x & 63) * 16;
    int w = threadIdx.x >> 5, lane = threadIdx.x & 31;
    {
        const float4* xs = (const float4*)(x + ((size_t)(t0 + w) * B_ + b) * H_);
        float4* d = (float4*)(sx + w * H_);
#pragma unroll
        for (int k = 0; k < 4; k++) d[lane + 32 * k] = xs[lane + 32 * k];
    }
    __syncthreads();
    int p = p0 + w;
    const float4* r0 = (const float4*)(src + ((size_t)b * P_ + p) * H_);
    float4 a0[4];
#pragma unroll
    for (int j = 0; j < 4; j++) a0[j] = r0[j * 32 + lane];
    float q0[C_];
#pragma unroll
    for (int t = 0; t < C_; t++) q0[t] = 0.f;
#pragma unroll
    for (int j = 0; j < 4; j++) {
#pragma unroll
        for (int t = 0; t < C_; t++) {
            float4 xv = *(const float4*)(sx + t * H_ + j * 128 + lane * 4);
            q0[t] += a0[j].x * xv.x + a0[j].y * xv.y + a0[j].z * xv.z + a0[j].w * xv.w;
        }
    }
#pragma unroll
    for (int t = 0; t < C_; t++) {
#pragma unroll
        for (int o = 16; o; o >>= 1)
            q0[t] += __shfl_xor_sync(~0u, q0[t], o);
    }
    float s0 = q0[0];
#pragma unroll
    for (int t = 1; t < C_; t++) s0 = (lane == t) ? q0[t] : s0;
    if (lane < C_)
        g_Q[buf][((size_t)b * P_ + p) * C_ + lane] = s0;
}

// ---------------------------------------------------------------------------
// Coefficient-space scan, DF trajectory (raw path bitwise == R9/R12).
// Gamma machinery removed (closed form in gamma_kernel); 2 barriers/step via
// double-buffered partials + redundant per-warp final reduction (identical
// op order -> bitwise-identical reductions).
// ---------------------------------------------------------------------------
extern __shared__ float s_dyn[];   // q: [C_][1024]

__global__ __launch_bounds__(1024, 1) void scan_kernel(int c) {
    __shared__ float sG[C_][C_];
    __shared__ float sXn[C_];
    __shared__ float s_redA[32];
    __shared__ float s_redB[32];
    float* s_q = s_dyn;

    int b = blockIdx.x;
    int p = threadIdx.x;
    int lane = p & 31, wid = p >> 5;
    if (p < 256) sG[p >> 4][p & 15] =
        g_G[(((size_t)b * NCH_ + c) * C_ + (p >> 4)) * C_ + (p & 15)];
    if (p < C_) sXn[p] = g_Xn[(c * C_ + p) * B_ + b];

    {
        const float4* q4 = (const float4*)(g_Q[c & 1] + ((size_t)b * P_ + p) * C_);
#pragma unroll
        for (int k = 0; k < 4; k++) {
            float4 v = q4[k];
            s_q[(4 * k + 0) * 1024 + p] = v.x;
            s_q[(4 * k + 1) * 1024 + p] = v.y;
            s_q[(4 * k + 2) * 1024 + p] = v.z;
            s_q[(4 * k + 3) * 1024 + p] = v.w;
        }
    }
    __syncthreads();

    float fh[C_], fl[C_];
    DF alpha; alpha.h = 1.f; alpha.l = 0.f;
    const DF D_DF  = {D_HI,  D_LO};
    const DF D2_DF = {D2_HI, D2_LO};
    const DF TD_DF = {TD_HI, TD_LO};

#pragma unroll
    for (int tl = 0; tl < C_; tl++) {
        DF acc = df_mul_f(alpha, s_q[tl * 1024 + p]);
#pragma unroll
        for (int s = 0; s < C_; s++) if (s < tl) {
            float g = sG[s][tl];
            float pp = __fmul_rn(fh[s], g);
            float ee = fmaf(fh[s], g, -pp);
            ee = fmaf(fl[s], g, ee);
            DF term; term.h = pp; term.l = ee;
            acc = df_add(acc, term);
        }
        float raw = __fadd_rn(acc.h, acc.l);

        // block max: warp partials -> every warp reduces redundantly
        float m = raw;
#pragma unroll
        for (int o = 16; o; o >>= 1) m = fmaxf(m, __shfl_xor_sync(~0u, m, o));
        if (lane == 0) s_redA[wid] = m;
        __syncthreads();
        {
            float v = s_redA[lane];
#pragma unroll
            for (int o = 16; o; o >>= 1) v = fmaxf(v, __shfl_xor_sync(~0u, v, o));
            m = v;
        }
        float thr = 0.9f * m, sc = 10.f / m;
        float logit = (raw >= thr) ? raw * sc : 0.f;
        float ex = __expf(logit - 10.f);
        float sum = ex;
#pragma unroll
        for (int o = 16; o; o >>= 1) sum += __shfl_xor_sync(~0u, sum, o);
        if (lane == 0) s_redB[wid] = sum;
        __syncthreads();
        {
            float v = s_redB[lane];
#pragma unroll
            for (int o = 16; o; o >>= 1) v += __shfl_xor_sync(~0u, v, o);
            sum = v;
        }
        float pr = ex / sum;

        g_W[((size_t)b * C_ + tl) * P_ + p] = fmaf(pr, alpha.l, __fmul_rn(pr, alpha.h));

        DF c2dpr = df_mul_f(TD_DF, pr);
        DF t1 = df_mul(c2dpr, acc);
        float ph = __fmul_rn(pr, pr);
        float pe = fmaf(pr, pr, -ph);
        DF prsq; prsq.h = ph; prsq.l = pe;
        DF t2 = df_mul_f(prsq, sXn[tl]);
        DF arg = df_add(df_add(D2_DF, t1), t2);

        float y0 = rsqrtf(arg.h);
        float qh = __fmul_rn(y0, y0);
        float qe = fmaf(y0, y0, -qh);
        DF y0sq; y0sq.h = qh; y0sq.l = qe;
        DF t = df_mul(arg, y0sq);
        DF negt; negt.h = -t.h; negt.l = -t.l;
        DF hdf = df_add_f(negt, 1.0f);
        float corr = 0.5f * y0 * __fadd_rn(hdf.h, hdf.l);
        DF inu = df_two_sum(y0, corr);

        DF r_ = df_mul(D_DF, inu);
#pragma unroll
        for (int s = 0; s < C_; s++) if (s < tl) {
            DF fs; fs.h = fh[s]; fs.l = fl[s];
            fs = df_mul(fs, r_);
            fh[s] = fs.h; fl[s] = fs.l;
        }
        DF ftl = df_mul_f(inu, pr);
        fh[tl] = ftl.h; fl[tl] = ftl.l;
        alpha = df_mul(alpha, r_);
    }

#pragma unroll
    for (int s = 0; s < C_; s++)
        g_Bc[((size_t)b * C_ + s) * P_ + p] = __fadd_rn(fh[s], fl[s]);
    g_A[b * P_ + p] = __fadd_rn(alpha.h, alpha.l);
}

// ---------------------------------------------------------------------------
// gamma[tl][s] = sum_p W[tl,p] * (Bc[s,p]/A[p])   (exact closed form; feeds
// out only — 1e-3 tolerance). One block per batch; e staged in 64KB smem.
// ---------------------------------------------------------------------------
__global__ __launch_bounds__(256) void gamma_kernel() {
    extern __shared__ float s_e[];   // [C_][1024]
    int b = blockIdx.x;
    int tid = threadIdx.x;
    for (int pp = tid; pp < P_; pp += 256) {
        float invA = 1.0f / g_A[b * P_ + pp];
#pragma unroll
        for (int s = 0; s < C_; s++)
            s_e[s * P_ + pp] = g_Bc[((size_t)b * C_ + s) * P_ + pp] * invA;
    }
    // zero the unused entries (s >= tl, incl. tl = 0 row)
    {
        int tl = tid >> 4, s = tid & 15;
        if (s >= tl) g_Gam[(b * C_ + tl) * C_ + s] = 0.f;
    }
    __syncthreads();
    int w = tid >> 5, lane = tid & 31;
    for (int id = w; id < 120; id += 8) {
        int tl = 1;
        while (tl * (tl + 1) / 2 <= id) tl++;
        int s = id - tl * (tl - 1) / 2;
        const float* Wp = g_W + ((size_t)b * C_ + tl) * P_;
        const float* ep = s_e + s * P_;
        float v = 0.f;
        for (int k = lane; k < P_; k += 32) v += Wp[k] * ep[k];
#pragma unroll
        for (int o = 16; o; o >>= 1) v += __shfl_xor_sync(~0u, v, o);
        if (lane == 0) g_Gam[(b * C_ + tl) * C_ + s] = v;
    }
}

// ---------------------------------------------------------------------------
// Apply with packed f32x2 FMA: new_pat = A*P0 + sum_s Bc[s]*x_s;
// out[t0+tl] += sum_p W[tl,p]*P0[p,:]. Coefficients pre-duplicated {c,c} in
// smem. Per-lane arithmetic order identical to R12 -> bitwise-identical pat.
// ---------------------------------------------------------------------------
__global__ __launch_bounds__(256) void apply_kernel(const float* __restrict__ x,
                                                    const float* __restrict__ pat_in,
                                                    float* __restrict__ out, int c) {
    __shared__ float sC2[64][68];   // [0..31]=B dup pairs, [32..63]=W dup, [64..65]=A dup
    __shared__ float sGm[C_ * C_];
    const float* src = (c == 0) ? pat_in : (const float*)g_pat;
    int b = blockIdx.x >> 4;
    int pt = blockIdx.x & 15;
    int p0 = pt * 64;
    int tid = threadIdx.x;
    int t0 = c * C_;

#pragma unroll
    for (int k = 0; k < 4; k++) {
        int i = tid + 256 * k;        // i < 1024
        int tl = i >> 6, r = i & 63;
        float bv = g_Bc[((size_t)b * C_ + tl) * P_ + p0 + r];
        float wv = g_W [((size_t)b * C_ + tl) * P_ + p0 + r];
        sC2[r][2 * tl] = bv;       sC2[r][2 * tl + 1] = bv;
        sC2[r][32 + 2 * tl] = wv;  sC2[r][32 + 2 * tl + 1] = wv;
    }
    if (tid < 64) {
        float av = g_A[b * P_ + p0 + tid];
        sC2[tid][64] = av; sC2[tid][65] = av;
    }
    if (pt == 0) sGm[tid] = g_Gam[b * 256 + tid];
    __syncthreads();

    int h = tid * 2;
    unsigned long long xp[C_];
#pragma unroll
    for (int s = 0; s < C_; s++)
        xp[s] = *(const unsigned long long*)(x + ((size_t)(t0 + s) * B_ + b) * H_ + h);
    unsigned long long accp[C_];
#pragma unroll
    for (int tl = 0; tl < C_; tl++) accp[tl] = 0ull;

    const float* sbase = src + ((size_t)b * P_ + p0) * H_ + h;
    float* dbase = g_pat + ((size_t)b * P_ + p0) * H_ + h;

    for (int r0 = 0; r0 < 64; r0 += 4) {
        unsigned long long pvp[4];
#pragma unroll
        for (int u = 0; u < 4; u++)
            pvp[u] = *(const unsigned long long*)(sbase + (size_t)(r0 + u) * H_);
#pragma unroll
        for (int u = 0; u < 4; u++) {
            int r = r0 + u;
            const ulonglong2* crow = (const ulonglong2*)&sC2[r][0];
            unsigned long long cb[16], cw[16];
#pragma unroll
            for (int k2 = 0; k2 < 8; k2++) {
                ulonglong2 v = crow[k2];
                cb[2 * k2] = v.x; cb[2 * k2 + 1] = v.y;
            }
#pragma unroll
            for (int k2 = 0; k2 < 8; k2++) {
                ulonglong2 v = crow[8 + k2];
                cw[2 * k2] = v.x; cw[2 * k2 + 1] = v.y;
            }
            unsigned long long a2 = *(const unsigned long long*)&sC2[r][64];
            unsigned long long nv = f2_mul(a2, pvp[u]);
#pragma unroll
            for (int s = 0; s < C_; s++)
                nv = f2_fma(cb[s], xp[s], nv);
            *(unsigned long long*)(dbase + (size_t)r * H_) = nv;
#pragma unroll
            for (int tl = 0; tl < C_; tl++)
                accp[tl] = f2_fma(cw[tl], pvp[u], accp[tl]);
        }
    }

    float2 acc[C_];
#pragma unroll
    for (int tl = 0; tl < C_; tl++) acc[tl] = f2_unpack(accp[tl]);

    if (pt == 0) {
#pragma unroll
        for (int tl = 0; tl < C_; tl++)
#pragma unroll
            for (int s = 0; s < C_; s++) {
                float g = sGm[tl * C_ + s];
                float2 xr = f2_unpack(xp[s]);
                acc[tl].x += g * xr.x; acc[tl].y += g * xr.y;
            }
    }
#pragma unroll
    for (int tl = 0; tl < C_; tl++) {
        float* op = out + ((size_t)(t0 + tl) * B_ + b) * H_ + h;
        atomicAdd(op, acc[tl].x);
        atomicAdd(op + 1, acc[tl].y);
    }
}

// ---------------------------------------------------------------------------
extern "C" void kernel_launch(void* const* d_in, const int* in_sizes, int n_in,
                              void* d_out, int out_size) {
    const float* x = (const float*)d_in[0];
    const float* pat = (const float*)d_in[1];
    if (n_in >= 2 && in_sizes[0] == B_ * P_ * H_) {
        x = (const float*)d_in[1];
        pat = (const float*)d_in[0];
    }
    float* out = (float*)d_out;

    const int scan_smem = C_ * 1024 * (int)sizeof(float);   // 64 KB dynamic
    cudaFuncSetAttribute(scan_kernel,
                         cudaFuncAttributeMaxDynamicSharedMemorySize, scan_smem);
    cudaFuncSetAttribute(gamma_kernel,
                         cudaFuncAttributeMaxDynamicSharedMemorySize, scan_smem);

    cudaMemsetAsync(d_out, 0, (size_t)out_size * sizeof(float), 0);
    xstats_kernel<<<B_ * NCH_, 256>>>(x);
    qk_kernel<<<B_ * 64, 512>>>(x, pat, 0, 0, 1);

    for (int c = 0; c < NCH_; c++) {
        scan_kernel<<<B_, 1024, scan_smem>>>(c);
        gamma_kernel<<<B_, 256, scan_smem>>>();
        apply_kernel<<<B_ * 16, 256>>>(x, pat, out, c);
        if (c + 1 < NCH_)
            qk_kernel<<<B_ * 64, 512>>>(x, pat, (c + 1) * C_, (c + 1) & 1, 0);
    }
}

// round 14
// speedup vs baseline: 1.2823x; 1.2823x over previous
#include <cuda_runtime.h>
#include <math.h>

#define T_ 256
#define B_ 64
#define P_ 1024
#define H_ 512
#define C_ 16
#define NCH_ (T_ / C_)
#define DECAY 0.999f

// Persistent scratch (static __device__ — no runtime allocation)
__device__ float g_pat[(size_t)B_ * P_ * H_];       // 128 MB carried state
__device__ float g_Q[2][(size_t)B_ * P_ * C_];      // Q[b][p][tau]
__device__ float g_W [(size_t)B_ * C_ * P_];        // W[b][tl][p] = pr*alpha_pre
__device__ float g_Bc[(size_t)B_ * C_ * P_];        // Bc[b][s][p] = f_s at chunk end
__device__ float g_A [B_ * P_];                     // alpha at chunk end
__device__ float g_G [B_ * NCH_ * C_ * C_];         // within-chunk Gram (fp64-accumulated)
__device__ float g_Xn[T_ * B_];                     // ||x_t||^2
__device__ float g_Gam[B_ * C_ * C_];               // gamma[b][tl][s]

// ===========================================================================
// Double-float (compensated fp32) helpers — exact R9/R12 versions.
// ===========================================================================
struct DF { float h, l; };

__device__ __forceinline__ DF df_renorm(float h, float l) {
    float s = __fadd_rn(h, l);
    float e = __fsub_rn(l, __fsub_rn(s, h));
    DF r; r.h = s; r.l = e; return r;
}
__device__ __forceinline__ DF df_two_sum(float a, float b) {
    float s = __fadd_rn(a, b);
    float bb = __fsub_rn(s, a);
    float e = __fadd_rn(__fsub_rn(a, __fsub_rn(s, bb)), __fsub_rn(b, bb));
    DF r; r.h = s; r.l = e; return r;
}
__device__ __forceinline__ DF df_mul(DF a, DF b) {
    float p = __fmul_rn(a.h, b.h);
    float e = fmaf(a.h, b.h, -p);
    e = fmaf(a.h, b.l, e);
    e = fmaf(a.l, b.h, e);
    return df_renorm(p, e);
}
__device__ __forceinline__ DF df_mul_f(DF a, float b) {
    float p = __fmul_rn(a.h, b);
    float e = fmaf(a.h, b, -p);
    e = fmaf(a.l, b, e);
    return df_renorm(p, e);
}
__device__ __forceinline__ DF df_add(DF a, DF b) {
    DF s = df_two_sum(a.h, b.h);
    float e = __fadd_rn(s.l, __fadd_rn(a.l, b.l));
    return df_renorm(s.h, e);
}
__device__ __forceinline__ DF df_add_f(DF a, float b) {
    DF s = df_two_sum(a.h, b);
    float e = __fadd_rn(s.l, a.l);
    return df_renorm(s.h, e);
}

#define D_HI   ((float)0.999)
#define D_LO   ((float)(0.999 - (double)((float)0.999)))
#define D2_HI  ((float)0.998001)
#define D2_LO  ((float)(0.998001 - (double)((float)0.998001)))
#define TD_HI  ((float)1.998)
#define TD_LO  ((float)(1.998 - (double)((float)1.998)))

// ---------------------------------------------------------------------------
// Gram + norms per (b, chunk): fp64 accumulation (tiny volume).
// ---------------------------------------------------------------------------
__global__ __launch_bounds__(256) void xstats_kernel(const float* __restrict__ x) {
    __shared__ float sx[C_ * H_];
    int b = blockIdx.x >> 4;
    int c = blockIdx.x & 15;
    int t0 = c * C_;
    {
        int tau = threadIdx.x >> 4, l16 = threadIdx.x & 15;
        const float4* xs = (const float4*)(x + ((size_t)(t0 + tau) * B_ + b) * H_);
        float4* d = (float4*)(sx + tau * H_);
#pragma unroll
        for (int k = 0; k < 8; k++) d[l16 + 16 * k] = xs[l16 + 16 * k];
    }
    __syncthreads();
    int w = threadIdx.x >> 5, lane = threadIdx.x & 31;
    for (int id = w; id < C_ * C_; id += 8) {
        int s = id >> 4, t = id & 15;
        if (s > t) continue;
        double acc = 0.0;
#pragma unroll
        for (int k = 0; k < 16; k++) {
            int h = lane + 32 * k;
            acc += (double)sx[s * H_ + h] * (double)sx[t * H_ + h];
        }
#pragma unroll
        for (int o = 16; o; o >>= 1) acc += __shfl_xor_sync(~0u, acc, o);
        if (lane == 0) {
            g_G[(((size_t)b * NCH_ + c) * C_ + s) * C_ + t] = (float)acc;
            if (s == t) g_Xn[(t0 + t) * B_ + b] = (float)acc;
        }
    }
}

// ---------------------------------------------------------------------------
// Q[buf][b][p][tau] = src_row(b,p) . x[t0+tau]   (R9 math, bitwise-identical)
// Block order REVERSED so qk reads pat in the opposite order apply wrote it:
// the most-recently-written 126MB-ish stays L2-resident -> L2 hits not DRAM.
// ---------------------------------------------------------------------------
__global__ __launch_bounds__(256) void qk_kernel(const float* __restrict__ x,
                                                 const float* __restrict__ pat_in,
                                                 int t0, int buf, int useInit) {
    __shared__ float sx[C_ * H_];
    const float* src = useInit ? pat_in : (const float*)g_pat;
    int bid = (B_ * 64 - 1) - blockIdx.x;   // descending traversal (L2 ping-pong)
    int b = bid >> 6;
    int p0 = (bid & 63) * 16;
    {
        int tau = threadIdx.x >> 4, l16 = threadIdx.x & 15;
        const float4* xs = (const float4*)(x + ((size_t)(t0 + tau) * B_ + b) * H_);
        float4* d = (float4*)(sx + tau * H_);
#pragma unroll
        for (int k = 0; k < 8; k++) d[l16 + 16 * k] = xs[l16 + 16 * k];
    }
    __syncthreads();
    int w = threadIdx.x >> 5, lane = threadIdx.x & 31;
    int p = p0 + w * 2;
    const float4* r0 = (const float4*)(src + ((size_t)b * P_ + p) * H_);
    const float4* r1 = (const float4*)(src + ((size_t)b * P_ + p + 1) * H_);
    float4 a0[4], a1[4];
#pragma unroll
    for (int j = 0; j < 4; j++) { a0[j] = r0[j * 32 + lane]; a1[j] = r1[j * 32 + lane]; }
    float q0[C_], q1[C_];
#pragma unroll
    for (int t = 0; t < C_; t++) { q0[t] = 0.f; q1[t] = 0.f; }
#pragma unroll
    for (int j = 0; j < 4; j++) {
#pragma unroll
        for (int t = 0; t < C_; t++) {
            float4 xv = *(const float4*)(sx + t * H_ + j * 128 + lane * 4);
            q0[t] += a0[j].x * xv.x + a0[j].y * xv.y + a0[j].z * xv.z + a0[j].w * xv.w;
            q1[t] += a1[j].x * xv.x + a1[j].y * xv.y + a1[j].z * xv.z + a1[j].w * xv.w;
        }
    }
#pragma unroll
    for (int t = 0; t < C_; t++) {
#pragma unroll
        for (int o = 16; o; o >>= 1) {
            q0[t] += __shfl_xor_sync(~0u, q0[t], o);
            q1[t] += __shfl_xor_sync(~0u, q1[t], o);
        }
    }
    float s0 = q0[0], s1 = q1[0];
#pragma unroll
    for (int t = 1; t < C_; t++) {
        s0 = (lane == t) ? q0[t] : s0;
        s1 = (lane == t) ? q1[t] : s1;
    }
    if (lane < C_) {
        g_Q[buf][((size_t)b * P_ + p) * C_ + lane] = s0;
        g_Q[buf][((size_t)b * P_ + p + 1) * C_ + lane] = s1;
    }
}

// ---------------------------------------------------------------------------
// Coefficient-space scan, trajectory state in double-float (exact R12 body,
// including in-loop gamma partials).
// ---------------------------------------------------------------------------
extern __shared__ float s_dyn[];   // q: [C_][1024]

__global__ __launch_bounds__(1024, 1) void scan_kernel(int c) {
    __shared__ float sG[C_][C_];
    __shared__ float sXn[C_];
    __shared__ float s_red[32];
    __shared__ float sval;
    __shared__ float sgp[120][33];
    float* s_q = s_dyn;

    int b = blockIdx.x;
    int p = threadIdx.x;
    int lane = p & 31, wid = p >> 5;
    if (p < 256) sG[p >> 4][p & 15] =
        g_G[(((size_t)b * NCH_ + c) * C_ + (p >> 4)) * C_ + (p & 15)];
    if (p < C_) sXn[p] = g_Xn[(c * C_ + p) * B_ + b];

    {
        const float4* q4 = (const float4*)(g_Q[c & 1] + ((size_t)b * P_ + p) * C_);
#pragma unroll
        for (int k = 0; k < 4; k++) {
            float4 v = q4[k];
            s_q[(4 * k + 0) * 1024 + p] = v.x;
            s_q[(4 * k + 1) * 1024 + p] = v.y;
            s_q[(4 * k + 2) * 1024 + p] = v.z;
            s_q[(4 * k + 3) * 1024 + p] = v.w;
        }
    }
    __syncthreads();

    float fh[C_], fl[C_];
    DF alpha; alpha.h = 1.f; alpha.l = 0.f;
    const DF D_DF  = {D_HI,  D_LO};
    const DF D2_DF = {D2_HI, D2_LO};
    const DF TD_DF = {TD_HI, TD_LO};

#pragma unroll
    for (int tl = 0; tl < C_; tl++) {
        DF acc = df_mul_f(alpha, s_q[tl * 1024 + p]);
#pragma unroll
        for (int s = 0; s < C_; s++) if (s < tl) {
            float g = sG[s][tl];
            float pp = __fmul_rn(fh[s], g);
            float ee = fmaf(fh[s], g, -pp);
            ee = fmaf(fl[s], g, ee);
            DF term; term.h = pp; term.l = ee;
            acc = df_add(acc, term);
        }
        float raw = __fadd_rn(acc.h, acc.l);

        float m = raw;
#pragma unroll
        for (int o = 16; o; o >>= 1) m = fmaxf(m, __shfl_xor_sync(~0u, m, o));
        if (lane == 0) s_red[wid] = m;
        __syncthreads();
        if (wid == 0) {
            float v = s_red[lane];
#pragma unroll
            for (int o = 16; o; o >>= 1) v = fmaxf(v, __shfl_xor_sync(~0u, v, o));
            if (lane == 0) sval = v;
        }
        __syncthreads();
        m = sval;
        float thr = 0.9f * m, sc = 10.f / m;
        float logit = (raw >= thr) ? raw * sc : 0.f;
        float ex = __expf(logit - 10.f);
        float sum = ex;
#pragma unroll
        for (int o = 16; o; o >>= 1) sum += __shfl_xor_sync(~0u, sum, o);
        if (lane == 0) s_red[wid] = sum;
        __syncthreads();
        if (wid == 0) {
            float v = s_red[lane];
#pragma unroll
            for (int o = 16; o; o >>= 1) v += __shfl_xor_sync(~0u, v, o);
            if (lane == 0) sval = v;
        }
        __syncthreads();
        float pr = ex / sval;

#pragma unroll
        for (int s = 0; s < C_; s++) if (s < tl) {
            float v = pr * fh[s];
#pragma unroll
            for (int o = 16; o; o >>= 1) v += __shfl_xor_sync(~0u, v, o);
            if (lane == 0) sgp[tl * (tl - 1) / 2 + s][wid] = v;
        }

        g_W[((size_t)b * C_ + tl) * P_ + p] = fmaf(pr, alpha.l, __fmul_rn(pr, alpha.h));

        DF c2dpr = df_mul_f(TD_DF, pr);
        DF t1 = df_mul(c2dpr, acc);
        float ph = __fmul_rn(pr, pr);
        float pe = fmaf(pr, pr, -ph);
        DF prsq; prsq.h = ph; prsq.l = pe;
        DF t2 = df_mul_f(prsq, sXn[tl]);
        DF arg = df_add(df_add(D2_DF, t1), t2);

        float y0 = rsqrtf(arg.h);
        float qh = __fmul_rn(y0, y0);
        float qe = fmaf(y0, y0, -qh);
        DF y0sq; y0sq.h = qh; y0sq.l = qe;
        DF t = df_mul(arg, y0sq);
        DF negt; negt.h = -t.h; negt.l = -t.l;
        DF hdf = df_add_f(negt, 1.0f);
        float corr = 0.5f * y0 * __fadd_rn(hdf.h, hdf.l);
        DF inu = df_two_sum(y0, corr);

        DF r_ = df_mul(D_DF, inu);
#pragma unroll
        for (int s = 0; s < C_; s++) if (s < tl) {
            DF fs; fs.h = fh[s]; fs.l = fl[s];
            fs = df_mul(fs, r_);
            fh[s] = fs.h; fl[s] = fs.l;
        }
        DF ftl = df_mul_f(inu, pr);
        fh[tl] = ftl.h; fl[tl] = ftl.l;
        alpha = df_mul(alpha, r_);
    }

#pragma unroll
    for (int s = 0; s < C_; s++)
        g_Bc[((size_t)b * C_ + s) * P_ + p] = __fadd_rn(fh[s], fl[s]);
    g_A[b * P_ + p] = __fadd_rn(alpha.h, alpha.l);

    __syncthreads();
    if (p < 256) {
        int tl = p >> 4, s = p & 15;
        float g = 0.f;
        if (s < tl) {
            int id = tl * (tl - 1) / 2 + s;
            for (int k = 0; k < 32; k++) g += sgp[id][k];
        }
        g_Gam[(b * C_ + tl) * C_ + s] = g;
    }
}

// ---------------------------------------------------------------------------
// Apply (R10's measured-best 128-row version): new_pat = A*P0 + sum_s Bc[s]*x_s;
// out[t0+tl] += sum_p W[tl,p]*P0[p,:] (+ gamma*x for ptile 0).
// Ascending block order (pairs with qk's descending for L2 ping-pong).
// ---------------------------------------------------------------------------
__global__ __launch_bounds__(256) void apply_kernel(const float* __restrict__ x,
                                                    const float* __restrict__ pat_in,
                                                    float* __restrict__ out, int c) {
    __shared__ float sC[128][36];   // [r][0..15]=B, [16..31]=W, [32]=A
    __shared__ float sGm[C_ * C_];
    const float* src = (c == 0) ? pat_in : (const float*)g_pat;
    int b = blockIdx.x >> 3;
    int pt = blockIdx.x & 7;
    int p0 = pt * 128;
    int tid = threadIdx.x;
    int t0 = c * C_;

#pragma unroll
    for (int k = 0; k < 8; k++) {
        int i = tid + 256 * k;
        int tl = i >> 7, r = i & 127;
        sC[r][tl]      = g_Bc[((size_t)b * C_ + tl) * P_ + p0 + r];
        sC[r][16 + tl] = g_W [((size_t)b * C_ + tl) * P_ + p0 + r];
    }
    if (tid < 128) sC[tid][32] = g_A[b * P_ + p0 + tid];
    if (pt == 0) sGm[tid] = g_Gam[b * 256 + tid];
    __syncthreads();

    int h = tid * 2;
    float2 xr[C_];
#pragma unroll
    for (int s = 0; s < C_; s++)
        xr[s] = *(const float2*)(x + ((size_t)(t0 + s) * B_ + b) * H_ + h);
    float2 acc[C_];
#pragma unroll
    for (int tl = 0; tl < C_; tl++) { acc[tl].x = 0.f; acc[tl].y = 0.f; }

    const float* sbase = src + ((size_t)b * P_ + p0) * H_ + h;
    float* dbase = g_pat + ((size_t)b * P_ + p0) * H_ + h;

    for (int r0 = 0; r0 < 128; r0 += 4) {
        float2 pv[4];
#pragma unroll
        for (int u = 0; u < 4; u++)
            pv[u] = *(const float2*)(sbase + (size_t)(r0 + u) * H_);
#pragma unroll
        for (int u = 0; u < 4; u++) {
            int r = r0 + u;
            float a = sC[r][32];
            float2 nv; nv.x = a * pv[u].x; nv.y = a * pv[u].y;
#pragma unroll
            for (int s = 0; s < C_; s++) {
                float bs = sC[r][s];
                nv.x += bs * xr[s].x; nv.y += bs * xr[s].y;
            }
            *(float2*)(dbase + (size_t)r * H_) = nv;
#pragma unroll
            for (int tl = 0; tl < C_; tl++) {
                float wv = sC[r][16 + tl];
                acc[tl].x += wv * pv[u].x; acc[tl].y += wv * pv[u].y;
            }
        }
    }
    if (pt == 0) {
#pragma unroll
        for (int tl = 0; tl < C_; tl++)
#pragma unroll
            for (int s = 0; s < C_; s++) {
                float g = sGm[tl * C_ + s];
                acc[tl].x += g * xr[s].x; acc[tl].y += g * xr[s].y;
            }
    }
#pragma unroll
    for (int tl = 0; tl < C_; tl++) {
        float* op = out + ((size_t)(t0 + tl) * B_ + b) * H_ + h;
        atomicAdd(op, acc[tl].x);
        atomicAdd(op + 1, acc[tl].y);
    }
}

// ---------------------------------------------------------------------------
extern "C" void kernel_launch(void* const* d_in, const int* in_sizes, int n_in,
                              void* d_out, int out_size) {
    const float* x = (const float*)d_in[0];
    const float* pat = (const float*)d_in[1];
    if (n_in >= 2 && in_sizes[0] == B_ * P_ * H_) {
        x = (const float*)d_in[1];
        pat = (const float*)d_in[0];
    }
    float* out = (float*)d_out;

    const int scan_smem = C_ * 1024 * (int)sizeof(float);   // 64 KB dynamic
    cudaFuncSetAttribute(scan_kernel,
                         cudaFuncAttributeMaxDynamicSharedMemorySize, scan_smem);

    cudaMemsetAsync(d_out, 0, (size_t)out_size * sizeof(float), 0);
    xstats_kernel<<<B_ * NCH_, 256>>>(x);
    qk_kernel<<<B_ * 64, 256>>>(x, pat, 0, 0, 1);

    for (int c = 0; c < NCH_; c++) {
        scan_kernel<<<B_, 1024, scan_smem>>>(c);
        apply_kernel<<<B_ * 8, 256>>>(x, pat, out, c);
        if (c + 1 < NCH_)
            qk_kernel<<<B_ * 64, 256>>>(x, pat, (c + 1) * C_, (c + 1) & 1, 0);
    }
}